// round 2
// baseline (speedup 1.0000x reference)
#include <cuda_runtime.h>

// GeneralMechanismODE: ordered bi-bi mechanism, 8 species, 4 reversible
// transitions, constant index tables folded into straight-line FMA code.
// Pure streaming kernel: 96 B read + 32 B written per row, touched once.
//
// R2: 2 rows per thread (8 independent LDG.128 front-batched), streaming
// cache hints (__ldcs / __stcs) since there is zero reuse.

__device__ __forceinline__ void row_compute(const float4& ylo, const float4& yhi,
                                            const float4& f, const float4& r,
                                            float4& olo, float4& ohi)
{
    float v0 = f.x * ylo.x * yhi.x - r.x * ylo.y;          // kf0*E*A  - kr0*EA
    float v1 = f.y * ylo.y * yhi.y - r.y * ylo.w;          // kf1*EA*B - kr1*EAB
    float v2 = f.z * ylo.w         - r.z * ylo.z * yhi.z;  // kf2*EAB  - kr2*EQ*P
    float v3 = f.w * ylo.z         - r.w * ylo.x * yhi.w;  // kf3*EQ   - kr3*E*Q

    olo.x = v3 - v0;   // dE
    olo.y = v0 - v1;   // dEA
    olo.z = v2 - v3;   // dEQ
    olo.w = v1 - v2;   // dEAB
    ohi.x = -v0;       // dA
    ohi.y = -v1;       // dB
    ohi.z = v2;        // dP
    ohi.w = v3;        // dQ
}

__global__ __launch_bounds__(256) void ode_kernel2(
    const float4* __restrict__ y,    // 2*B float4
    const float4* __restrict__ kf,   // B float4
    const float4* __restrict__ kr,   // B float4
    float4* __restrict__ out,        // 2*B float4
    int B)
{
    int g = blockIdx.x * blockDim.x + threadIdx.x;   // thread handles rows 2g, 2g+1
    int b0 = 2 * g;
    if (b0 >= B) return;

    // Front-batch all 8 independent 128-bit streaming loads (MLP=8).
    float4 ylo0 = __ldcs(&y[4 * g + 0]);
    float4 yhi0 = __ldcs(&y[4 * g + 1]);
    float4 ylo1 = __ldcs(&y[4 * g + 2]);
    float4 yhi1 = __ldcs(&y[4 * g + 3]);
    float4 f0   = __ldcs(&kf[b0 + 0]);
    float4 f1   = __ldcs(&kf[b0 + 1]);
    float4 r0   = __ldcs(&kr[b0 + 0]);
    float4 r1   = __ldcs(&kr[b0 + 1]);

    float4 olo0, ohi0, olo1, ohi1;
    row_compute(ylo0, yhi0, f0, r0, olo0, ohi0);
    row_compute(ylo1, yhi1, f1, r1, olo1, ohi1);

    __stcs(&out[4 * g + 0], olo0);
    __stcs(&out[4 * g + 1], ohi0);
    if (b0 + 1 < B) {
        __stcs(&out[4 * g + 2], olo1);
        __stcs(&out[4 * g + 3], ohi1);
    }
}

extern "C" void kernel_launch(void* const* d_in, const int* in_sizes, int n_in,
                              void* d_out, int out_size)
{
    // metadata order: t (1), y (B*8), forward_rates (B*4), reverse_rates (B*4)
    const float4* y  = (const float4*)d_in[1];
    const float4* kf = (const float4*)d_in[2];
    const float4* kr = (const float4*)d_in[3];
    float4* out = (float4*)d_out;

    int B = in_sizes[1] / 8;               // 2,000,000 (even, but guard anyway)
    int pairs = (B + 1) / 2;
    int threads = 256;
    int blocks = (pairs + threads - 1) / threads;
    ode_kernel2<<<blocks, threads>>>(y, kf, kr, out, B);
}

// round 3
// speedup vs baseline: 1.1169x; 1.1169x over previous
#include <cuda_runtime.h>

// GeneralMechanismODE: ordered bi-bi mechanism, 8 species, 4 reversible
// transitions, constant index tables folded to straight-line FMAs.
// Pure single-touch streaming: 96 B read + 32 B written per row.
//
// R3: R1 structure (1 row/thread, low regs, high occupancy — proven best)
// + evict-first streaming hints only. R2 showed that trading occupancy for
// per-thread MLP regresses; occupancy is the binding resource here.

__global__ __launch_bounds__(256) void ode_kernel3(
    const float4* __restrict__ y,    // 2*B float4
    const float4* __restrict__ kf,   // B float4
    const float4* __restrict__ kr,   // B float4
    float4* __restrict__ out,        // 2*B float4
    int B)
{
    int b = blockIdx.x * blockDim.x + threadIdx.x;
    if (b >= B) return;

    // 4 independent 128-bit streaming loads, front-batched.
    float4 ylo = __ldcs(&y[2 * b + 0]);   // y0..y3
    float4 yhi = __ldcs(&y[2 * b + 1]);   // y4..y7
    float4 f   = __ldcs(&kf[b]);
    float4 r   = __ldcs(&kr[b]);

    float v0 = f.x * ylo.x * yhi.x - r.x * ylo.y;          // kf0*E*A  - kr0*EA
    float v1 = f.y * ylo.y * yhi.y - r.y * ylo.w;          // kf1*EA*B - kr1*EAB
    float v2 = f.z * ylo.w         - r.z * ylo.z * yhi.z;  // kf2*EAB  - kr2*EQ*P
    float v3 = f.w * ylo.z         - r.w * ylo.x * yhi.w;  // kf3*EQ   - kr3*E*Q

    float4 olo, ohi;
    olo.x = v3 - v0;   // dE
    olo.y = v0 - v1;   // dEA
    olo.z = v2 - v3;   // dEQ
    olo.w = v1 - v2;   // dEAB
    ohi.x = -v0;       // dA
    ohi.y = -v1;       // dB
    ohi.z = v2;        // dP
    ohi.w = v3;        // dQ

    __stcs(&out[2 * b + 0], olo);
    __stcs(&out[2 * b + 1], ohi);
}

extern "C" void kernel_launch(void* const* d_in, const int* in_sizes, int n_in,
                              void* d_out, int out_size)
{
    // metadata order: t (1), y (B*8), forward_rates (B*4), reverse_rates (B*4)
    const float4* y  = (const float4*)d_in[1];
    const float4* kf = (const float4*)d_in[2];
    const float4* kr = (const float4*)d_in[3];
    float4* out = (float4*)d_out;

    int B = in_sizes[1] / 8;
    int threads = 256;
    int blocks = (B + threads - 1) / threads;
    ode_kernel3<<<blocks, threads>>>(y, kf, kr, out, B);
}